// round 5
// baseline (speedup 1.0000x reference)
#include <cuda_runtime.h>
#include <cuda_bf16.h>
#include <math_constants.h>

// ShiftNMF: V[n,m] = sum_d softplus(W[n,d]) * exp(-2*pi*i*tau[n,d]*m/M) * Hft[d,m]
// Hft = full FFT of softplus(H) (reference's rfft+mirror == full FFT of real signal).
// Harness output dtype is float32: expected = Re(V), shape (N, M), out_size = N*M.

#define N_ROWS 1024
#define RANK   16
#define M_LEN  4096
#define LOG2M  12

__device__ float2 g_Hft[RANK * M_LEN];   // device-global scratch (no allocation)

__device__ __forceinline__ float softplus_accurate(float x) {
    return (x > 20.0f) ? x : log1pf(expf(x));
}

// ---------------------------------------------------------------------------
// Kernel 1: 16 x 4096-pt FFT of softplus(H) rows. One CTA per row.
// Twiddles precomputed once into shared (w[j] = exp(-2*pi*i*j/M), j < M/2).
// ---------------------------------------------------------------------------
__global__ void __launch_bounds__(512) fft_hft_kernel(const float* __restrict__ H) {
    __shared__ float2 buf[M_LEN];        // 32 KB
    __shared__ float2 tw[M_LEN / 2];     // 16 KB twiddle table
    const int row = blockIdx.x;
    const int tid = threadIdx.x;

    for (int j = tid; j < M_LEN / 2; j += 512) {
        float s, c;
        sincospif(-2.0f * (float)j / (float)M_LEN, &s, &c);
        tw[j] = make_float2(c, s);
    }
    for (int i = tid; i < M_LEN; i += 512) {
        int j = __brev((unsigned)i) >> (32 - LOG2M);
        float v = softplus_accurate(H[row * M_LEN + i]);
        buf[j] = make_float2(v, 0.0f);
    }
    __syncthreads();

    #pragma unroll 1
    for (int s = 1; s <= LOG2M; s++) {
        const int half = 1 << (s - 1);
        const int tsh  = LOG2M - s;      // twiddle index = k << tsh
        for (int j = tid; j < (M_LEN / 2); j += 512) {
            int k   = j & (half - 1);
            int grp = j >> (s - 1);
            int i1  = grp * (half << 1) + k;
            int i2  = i1 + half;
            float2 w = tw[k << tsh];
            float2 a = buf[i1];
            float2 b = buf[i2];
            float tr = w.x * b.x - w.y * b.y;
            float ti = w.x * b.y + w.y * b.x;
            buf[i2] = make_float2(a.x - tr, a.y - ti);
            buf[i1] = make_float2(a.x + tr, a.y + ti);
        }
        __syncthreads();
    }

    for (int i = tid; i < M_LEN; i += 512) {
        g_Hft[row * M_LEN + i] = buf[i];
    }
}

// ---------------------------------------------------------------------------
// Kernel 2: out[n,m] = Re( sum_d c_nd(m) * Hft[d,m] ),
// c_nd(m) = softplus(W[n,d]) * exp(-2*pi*i*tau[n,d]*m/M).
// Warp owns one n; lanes span m. 16 register rotators per lane, stepped by
// exp(-2*pi*i*tau*32/M) per iteration; exact re-seed each 256-m tile.
// ---------------------------------------------------------------------------
#define CHUNK 256
#define WARPS_PER_CTA 8
#define ITERS (CHUNK / 32)

__global__ void __launch_bounds__(256) shiftnmf_main_kernel(
    const float* __restrict__ W,
    const float* __restrict__ tau,
    float* __restrict__ out,            // (N, M) float32: Re(V)
    unsigned long long max_elems)       // write guard (float32 count)
{
    __shared__ float2 sh[RANK * CHUNK];  // 32 KB, [d][m_local]

    const int tid    = threadIdx.x;
    const int lane   = tid & 31;
    const int warp   = tid >> 5;
    const int m_base = blockIdx.x * CHUNK;
    const int n      = blockIdx.y * WARPS_PER_CTA + warp;

    for (int idx = tid; idx < RANK * CHUNK; idx += 256) {
        int d  = idx >> 8;              // / CHUNK
        int ml = idx & (CHUNK - 1);
        sh[idx] = g_Hft[d * M_LEN + m_base + ml];
    }
    __syncthreads();

    float cr[RANK], ci[RANK], wr[RANK], wi[RANK];
    const float inv_m = 1.0f / (float)M_LEN;
    const int m0 = m_base + lane;

    #pragma unroll
    for (int d = 0; d < RANK; d++) {
        float t  = tau[n * RANK + d];
        float sw = softplus_accurate(W[n * RANK + d]);
        float s0, c0;
        sincospif(-2.0f * t * ((float)m0 * inv_m), &s0, &c0);
        cr[d] = sw * c0;
        ci[d] = sw * s0;
        float ss, cs;
        sincospif(-2.0f * t * (32.0f * inv_m), &ss, &cs);
        wr[d] = cs;
        wi[d] = ss;
    }

    const unsigned long long row_base =
        (unsigned long long)n * M_LEN + m_base;

    #pragma unroll 1
    for (int it = 0; it < ITERS; it++) {
        const int ml = it * 32 + lane;
        float ar = 0.0f;
        #pragma unroll
        for (int d = 0; d < RANK; d++) {
            float2 h = sh[d * CHUNK + ml];
            // Re( c * h )
            ar = fmaf(cr[d], h.x, ar);
            ar = fmaf(-ci[d], h.y, ar);
            // rotate: c *= om
            float nr = cr[d] * wr[d] - ci[d] * wi[d];
            float ni = cr[d] * wi[d] + ci[d] * wr[d];
            cr[d] = nr;
            ci[d] = ni;
        }
        unsigned long long fi = row_base + (unsigned long long)ml;
        if (fi < max_elems) {
            out[fi] = ar;
        }
    }
}

// ---------------------------------------------------------------------------
extern "C" void kernel_launch(void* const* d_in, const int* in_sizes, int n_in,
                              void* d_out, int out_size) {
    // H = strictly largest input; remaining two in given order = W, tau_tilde.
    int hi = 0;
    for (int i = 1; i < n_in; i++)
        if (in_sizes[i] > in_sizes[hi]) hi = i;

    const float* H = (const float*)d_in[hi];
    const float* wt[2] = {nullptr, nullptr};
    int nwt = 0;
    for (int i = 0; i < n_in && nwt < 2; i++)
        if (i != hi) wt[nwt++] = (const float*)d_in[i];
    const float* W   = wt[0];
    const float* tau = (wt[1] != nullptr) ? wt[1] : wt[0];

    float* out = (float*)d_out;

    // Buffer = out_size float32 elements (established: round-3 writes of
    // exactly out_size floats were clean; 2*out_size faulted).
    unsigned long long max_elems = (unsigned long long)out_size;
    const unsigned long long full = (unsigned long long)N_ROWS * M_LEN;
    if (max_elems > full) max_elems = full;

    fft_hft_kernel<<<RANK, 512>>>(H);

    dim3 grid(M_LEN / CHUNK, N_ROWS / WARPS_PER_CTA);  // (16, 128)
    shiftnmf_main_kernel<<<grid, 256>>>(W, tau, out, max_elems);
}

// round 6
// speedup vs baseline: 1.6743x; 1.6743x over previous
#include <cuda_runtime.h>
#include <cuda_bf16.h>
#include <math_constants.h>

// ShiftNMF: out[n,m] = Re( sum_d softplus(W[n,d]) * exp(-2*pi*i*tau[n,d]*m/M) * Hft[d,m] )
// Hft = full FFT of softplus(H) (reference's rfft+mirror == full FFT of real signal).
// Output dtype float32 (harness coerces complex ref to real part), out_size = N*M.

#define N_ROWS 1024
#define RANK   16
#define M_LEN  4096
#define LOG2M  12

__device__ float2 g_Hft[RANK * M_LEN];   // device-global scratch (no allocation)

__device__ __forceinline__ float softplus_accurate(float x) {
    return (x > 20.0f) ? x : log1pf(expf(x));
}

// ---------------------------------------------------------------------------
// Kernel 1: 16 x 4096-pt FFT of softplus(H) rows. One CTA per row, 1024 thr.
// Twiddles precomputed once into shared.
// ---------------------------------------------------------------------------
#define FFT_THREADS 1024

__global__ void __launch_bounds__(FFT_THREADS) fft_hft_kernel(const float* __restrict__ H) {
    __shared__ float2 buf[M_LEN];        // 32 KB
    __shared__ float2 tw[M_LEN / 2];     // 16 KB twiddle table
    const int row = blockIdx.x;
    const int tid = threadIdx.x;

    for (int j = tid; j < M_LEN / 2; j += FFT_THREADS) {
        float s, c;
        sincospif(-2.0f * (float)j / (float)M_LEN, &s, &c);
        tw[j] = make_float2(c, s);
    }
    for (int i = tid; i < M_LEN; i += FFT_THREADS) {
        int j = __brev((unsigned)i) >> (32 - LOG2M);
        float v = softplus_accurate(H[row * M_LEN + i]);
        buf[j] = make_float2(v, 0.0f);
    }
    __syncthreads();

    #pragma unroll 1
    for (int s = 1; s <= LOG2M; s++) {
        const int half = 1 << (s - 1);
        const int tsh  = LOG2M - s;      // twiddle index = k << tsh
        for (int j = tid; j < (M_LEN / 2); j += FFT_THREADS) {
            int k   = j & (half - 1);
            int grp = j >> (s - 1);
            int i1  = grp * (half << 1) + k;
            int i2  = i1 + half;
            float2 w = tw[k << tsh];
            float2 a = buf[i1];
            float2 b = buf[i2];
            float tr = w.x * b.x - w.y * b.y;
            float ti = w.x * b.y + w.y * b.x;
            buf[i2] = make_float2(a.x - tr, a.y - ti);
            buf[i1] = make_float2(a.x + tr, a.y + ti);
        }
        __syncthreads();
    }

    for (int i = tid; i < M_LEN; i += FFT_THREADS) {
        g_Hft[row * M_LEN + i] = buf[i];
    }
}

// ---------------------------------------------------------------------------
// Kernel 2: warp owns one n; lanes span m; CTA covers 512 m.
// Two d-passes of 8 ranks each. Rotators advance with the Chebyshev
// recurrence x_{j+1} = k*x_j - x_{j-1}, k = 2*cos(2*pi*tau*32/M):
// 1 FFMA per component per 32-m step (vs 4-op complex rotate).
// ---------------------------------------------------------------------------
#define CHUNK_M 512
#define SUB_M   256
#define DPASS   8
#define WARPS_PER_CTA 8

__global__ void __launch_bounds__(256, 3) shiftnmf_main_kernel(
    const float* __restrict__ W,
    const float* __restrict__ tau,
    float* __restrict__ out,            // (N, M) float32: Re(V)
    unsigned long long max_elems)
{
    __shared__ float2 sh[DPASS * SUB_M];  // 16 KB, [d][m_local]

    const int tid    = threadIdx.x;
    const int lane   = tid & 31;
    const int warp   = tid >> 5;
    const int m_base = blockIdx.x * CHUNK_M;
    const int n      = blockIdx.y * WARPS_PER_CTA + warp;

    float acc[16];
    #pragma unroll
    for (int i = 0; i < 16; i++) acc[i] = 0.0f;

    const float inv_m = 1.0f / (float)M_LEN;
    const int m0 = m_base + lane;

    #pragma unroll 1
    for (int pass = 0; pass < 2; pass++) {
        const int dbase = pass * DPASS;

        // Seed 8 rotators: cur = sp(W)*exp(-2*pi*i*tau*m0/M),
        // prev = cur * conj(om), om = exp(-2*pi*i*tau*32/M), k = 2*Re(om).
        float xc[DPASS], xp[DPASS], yc[DPASS], yp[DPASS], kk[DPASS];
        #pragma unroll
        for (int d = 0; d < DPASS; d++) {
            float t  = tau[n * RANK + dbase + d];
            float sw = softplus_accurate(W[n * RANK + dbase + d]);
            float s0, c0;
            sincospif(-2.0f * t * ((float)m0 * inv_m), &s0, &c0);
            float cr = sw * c0;
            float ci = sw * s0;
            float ss, cs;
            sincospif(-2.0f * t * (32.0f * inv_m), &ss, &cs);   // om = (cs, ss)
            kk[d] = 2.0f * cs;
            xc[d] = cr;
            yc[d] = ci;
            // prev = cur * conj(om): (cr + i*ci)(cs - i*ss)
            xp[d] = fmaf(cr, cs,  ci * ss);
            yp[d] = fmaf(ci, cs, -cr * ss);
        }

        #pragma unroll
        for (int st = 0; st < 2; st++) {
            __syncthreads();
            // Cooperative load of this pass's 8 rows x 256 m (float4 = 2 complex)
            #pragma unroll
            for (int q = 0; q < (DPASS * SUB_M / 2) / 256; q++) {   // 4 iters
                int idx = q * 256 + tid;
                int d   = idx >> 7;                 // / (SUB_M/2)
                int e   = idx & (SUB_M / 2 - 1);    // float4 index in row
                float4 v = *reinterpret_cast<const float4*>(
                    &g_Hft[(dbase + d) * M_LEN + m_base + st * SUB_M + e * 2]);
                *reinterpret_cast<float4*>(&sh[d * SUB_M + e * 2]) = v;
            }
            __syncthreads();

            #pragma unroll
            for (int it = 0; it < 8; it++) {
                const int ml = it * 32 + lane;
                float a = acc[st * 8 + it];
                #pragma unroll
                for (int d = 0; d < DPASS; d++) {
                    float2 h = sh[d * SUB_M + ml];
                    a = fmaf(xc[d], h.x, a);
                    a = fmaf(-yc[d], h.y, a);
                    // Chebyshev advance (both components share k)
                    float xn = fmaf(kk[d], xc[d], -xp[d]);
                    float yn = fmaf(kk[d], yc[d], -yp[d]);
                    xp[d] = xc[d]; xc[d] = xn;
                    yp[d] = yc[d]; yc[d] = yn;
                }
                acc[st * 8 + it] = a;
            }
        }
    }

    const unsigned long long row_base = (unsigned long long)n * M_LEN + m_base;
    #pragma unroll
    for (int i = 0; i < 16; i++) {
        unsigned long long fi = row_base + (unsigned long long)(i * 32 + lane);
        if (fi < max_elems) out[fi] = acc[i];
    }
}

// ---------------------------------------------------------------------------
extern "C" void kernel_launch(void* const* d_in, const int* in_sizes, int n_in,
                              void* d_out, int out_size) {
    // H = strictly largest input; remaining two in given order = W, tau_tilde.
    int hi = 0;
    for (int i = 1; i < n_in; i++)
        if (in_sizes[i] > in_sizes[hi]) hi = i;

    const float* H = (const float*)d_in[hi];
    const float* wt[2] = {nullptr, nullptr};
    int nwt = 0;
    for (int i = 0; i < n_in && nwt < 2; i++)
        if (i != hi) wt[nwt++] = (const float*)d_in[i];
    const float* W   = wt[0];
    const float* tau = (wt[1] != nullptr) ? wt[1] : wt[0];

    float* out = (float*)d_out;

    unsigned long long max_elems = (unsigned long long)out_size;
    const unsigned long long full = (unsigned long long)N_ROWS * M_LEN;
    if (max_elems > full) max_elems = full;

    fft_hft_kernel<<<RANK, FFT_THREADS>>>(H);

    dim3 grid(M_LEN / CHUNK_M, N_ROWS / WARPS_PER_CTA);  // (8, 128)
    shiftnmf_main_kernel<<<grid, 256>>>(W, tau, out, max_elems);
}